// round 13
// baseline (speedup 1.0000x reference)
#include <cuda_runtime.h>
#include <cstdint>

// BestChangeLayer: B batches, 25x25 binary grids, 512 candidate 3x3 patterns,
// one Conway step on a 7x7 window, L1 error on inner 5x5 vs target,
// argmin(err + 0.5*noise), write winning pattern into x at (ry, rx).
//
// Bitboards: 7x7 packed in u64 at bit (r*8 + c).
// 256 threads/block, one batch per block, 2 patterns per thread
// (p = 2*tid + j; j toggles board bit 36). Shared CSA once per thread;
// variant j=1 ripple-adds the constant neighbor mask of cell (4,4).

#define NPAT 512
typedef unsigned long long u64;

#define REDOR64(v) ( ((u64)__reduce_or_sync(0xffffffffu,(unsigned)((v) >> 32)) << 32) \
                   |  (u64)__reduce_or_sync(0xffffffffu,(unsigned)(v)) )

__global__ __launch_bounds__(256, 6)
void bcl_kernel(const float* __restrict__ x,
                const float* __restrict__ target,
                const float* __restrict__ noise,
                const int* __restrict__ ryp,
                const int* __restrict__ rxp,
                float* __restrict__ out)
{
    __shared__ u64 s_fixed;   // 7x7 influence, center 3x3 cleared
    __shared__ u64 s_targ;    // 5x5 target at rows/cols 1..5
    __shared__ u64 sk[8];     // per-warp best (float_bits<<32)|pattern_idx

    const int tid  = threadIdx.x;
    const int warp = tid >> 5;
    const int lane = tid & 31;
    const int b    = blockIdx.x;

    const float* __restrict__ xb = x + b * 625;
    float* __restrict__ ob = out + b * 625;

    // ---- All global loads up front (coalesced / independent) ----
    const float2 nz = ((const float2*)noise)[b * 256 + tid];

    float x0 = xb[tid];
    float x1 = xb[tid + 256];
    float x2 = (tid < 113) ? xb[tid + 512] : 0.0f;

    const int ry = *ryp, rx = *rxp;

    // Warp-specialized gathers (periodic indexing; lines warmed by the
    // copy loads above, so these are mostly L1/L2 hits).
    if (warp == 0) {
        // 7x7 influence window, center 3x3 cleared.
        u64 pf = 0;
        #pragma unroll
        for (int it = 0; it < 2; it++) {
            int item = lane + it * 32;
            if (item < 49) {
                int r = item / 7, c = item % 7;
                if (!(r >= 2 && r <= 4 && c >= 2 && c <= 4)) {
                    int rr = (ry + 23 + r) % 25;
                    int cc = (rx + 23 + c) % 25;
                    if (xb[rr * 25 + cc] != 0.0f) pf |= 1ULL << (r * 8 + c);
                }
            }
        }
        u64 f = REDOR64(pf);
        if (lane == 0) s_fixed = f;
    } else if (warp == 1) {
        // 5x5 target window.
        const float* __restrict__ tb = target + b * 625;
        u64 pt = 0;
        if (lane < 25) {
            int r = lane / 5, c = lane % 5;
            int rr = (ry + 24 + r) % 25;
            int cc = (rx + 24 + c) % 25;
            if (tb[rr * 25 + cc] != 0.0f) pt |= 1ULL << ((r + 1) * 8 + (c + 1));
        }
        u64 tg = REDOR64(pt);
        if (lane == 0) s_targ = tg;
    }

    // Copy x -> out (values already in registers).
    ob[tid]       = x0;
    ob[tid + 256] = x1;
    if (tid < 113) ob[tid + 512] = x2;

    // Base pattern mask: p = 2*tid + j. Element k (r=k/3,c=k%3) of pattern p
    // is (p >> (8-k)) & 1 at board bit (2+r)*8+(2+c):
    //   tid bits 7..5 -> board 18..20 (reversed triple), 4..2 -> 26..28
    //   (reversed), bit1 -> 34, bit0 -> 35; j -> 36.
    const u64 base = ((u64)(__brev((tid >> 5) & 7) >> 29) << 18)
                   | ((u64)(__brev((tid >> 2) & 7) >> 29) << 26)
                   | ((u64)((tid >> 1) & 1) << 34)
                   | ((u64)(tid & 1) << 35);

    __syncthreads();

    const u64 targ = s_targ;
    const u64 Bc   = s_fixed | base;            // board without bit 36
    const u64 M    = 0x007F7F7F7F7F7F7FULL;     // col-shift guard
    const u64 CROP = 0x00003E3E3E3E3E00ULL;     // rows 1..5, cols 1..5
    const u64 B36  = 1ULL << 36;
    const u64 M36  = 0x0000382838000000ULL;     // neighbors of cell (4,4)

    // One CSA over the 8 neighbor planes of Bc -> bit-sliced count:
    //   cc0 = count bit0, cc1 = parity of weight-2 sum, hi = sum >= 2.
    // alive: cc1 & ~hi & (cc0 | cell).
    u64 n1 = (Bc << 1) & M, n2 = (Bc >> 1) & M;
    u64 n3 = Bc << 8,  n4 = Bc >> 8;
    u64 n5 = n1 << 8,  n6 = n1 >> 8;
    u64 n7 = n2 << 8,  n8 = n2 >> 8;

    u64 a1 = n1 ^ n2, b1 = n1 & n2;
    u64 a2 = n3 ^ n4, b2 = n3 & n4;
    u64 a3 = n5 ^ n6, b3 = n5 & n6;
    u64 a4 = n7 ^ n8, b4 = n7 & n8;

    u64 s1 = a1 ^ a2, t1 = a1 & a2;
    u64 s2 = a3 ^ a4, t2 = a3 & a4;
    u64 cc0 = s1 ^ s2, u0 = s1 & s2;

    u64 p1 = b1 ^ b2, q1 = b1 & b2;
    u64 p2 = b3 ^ b4, q2 = b3 & b4;
    u64 p3 = t1 ^ t2, q3 = t1 & t2;
    u64 r1 = p1 ^ p2, w1 = p1 & p2;
    u64 r2 = p3 ^ u0, w2 = p3 & u0;
    u64 cc1 = r1 ^ r2, w3 = r1 & r2;
    u64 hi = q1 | q2 | q3 | w1 | w2 | w3;

    u64 bestKey;
    // j = 0: no toggle.
    {
        u64 nx = cc1 & ~hi & (cc0 | Bc);
        int err = __popcll((nx & CROP) ^ targ);
        float sd = (float)err + nz.x * 0.5f;
        bestKey = ((u64)__float_as_uint(sd) << 32) | (unsigned)(2 * tid);
    }
    // j = 1: +bit36 -> ripple-add M36 into the bit-sliced count (exact).
    {
        u64 k0 = cc0 & M36, a0v = cc0 ^ M36;
        u64 av = cc1 ^ k0,  h   = hi | (cc1 & k0);
        u64 nx = av & ~h & (a0v | Bc | B36);
        int err = __popcll((nx & CROP) ^ targ);
        float sd = (float)err + nz.y * 0.5f;
        u64 key = ((u64)__float_as_uint(sd) << 32) | (unsigned)(2 * tid + 1);
        if (key < bestKey) bestKey = key;
    }

    // Warp argmin (packed key => value min, first-index tiebreak).
    #pragma unroll
    for (int s = 16; s; s >>= 1) {
        u64 o = __shfl_xor_sync(0xffffffffu, bestKey, s);
        if (o < bestKey) bestKey = o;
    }
    if (lane == 0) sk[warp] = bestKey;

    __syncthreads();   // publishes sk; orders copy stores before patch

    if (tid < 9) {
        u64 k0 = sk[0];
        #pragma unroll
        for (int w = 1; w < 8; w++) if (sk[w] < k0) k0 = sk[w];
        int best = (int)(unsigned)k0;
        float vv = ((best >> (8 - tid)) & 1) ? 1.0f : 0.0f;
        ob[(ry + tid / 3) * 25 + (rx + tid % 3)] = vv;
    }
}

extern "C" void kernel_launch(void* const* d_in, const int* in_sizes, int n_in,
                              void* d_out, int out_size)
{
    const float* x      = (const float*)d_in[0];
    const float* target = (const float*)d_in[1];
    const float* noise  = (const float*)d_in[2];
    const int*   ryp    = (const int*)d_in[3];
    const int*   rxp    = (const int*)d_in[4];
    float* out = (float*)d_out;

    int B = in_sizes[0] / 625;
    bcl_kernel<<<B, 256>>>(x, target, noise, ryp, rxp, out);
}

// round 14
// speedup vs baseline: 1.0078x; 1.0078x over previous
#include <cuda_runtime.h>
#include <cstdint>

// BestChangeLayer: B batches, 25x25 binary grids, 512 candidate 3x3 patterns,
// one Conway step on a 7x7 window, L1 error on inner 5x5 vs target,
// argmin(err + 0.5*noise), write winning pattern into x at (ry, rx).
//
// Bitboards: 7x7 packed in u64 at bit (r*8 + c).
// 128 threads/block, one batch per block, 4 patterns per thread:
// p = 4*tid + j; j toggles board bits 35/36. One shared CSA per thread;
// variants ripple-add the constant neighbor masks of cells (4,3)/(4,4).

#define NPAT 512
typedef unsigned long long u64;

#define REDOR64(v) ( ((u64)__reduce_or_sync(0xffffffffu,(unsigned)((v) >> 32)) << 32) \
                   |  (u64)__reduce_or_sync(0xffffffffu,(unsigned)(v)) )

__global__ __launch_bounds__(128, 8)
void bcl_kernel(const float* __restrict__ x,
                const float* __restrict__ target,
                const float* __restrict__ noise,
                const int* __restrict__ ryp,
                const int* __restrict__ rxp,
                float* __restrict__ out)
{
    __shared__ u64 s_fixed;   // 7x7 influence, center 3x3 cleared
    __shared__ u64 s_targ;    // 5x5 target at rows/cols 1..5
    __shared__ u64 sk[4];     // per-warp best (float_bits<<32)|pattern_idx

    const int b    = blockIdx.x;
    const int tid  = threadIdx.x;
    const int warp = tid >> 5;
    const int lane = tid & 31;

    const float* __restrict__ xb = x + b * 625;
    float* __restrict__ ob = out + b * 625;

    const int ry = *ryp, rx = *rxp;

    // ---- Critical-path gathers first (warp-specialized, scattered LDGs) ----
    if (warp == 0) {
        // 7x7 influence window, center 3x3 cleared. Periodic indexing via
        // conditional subtracts (ry,rx in [0,24] => v in [23,53]).
        u64 pf = 0;
        #pragma unroll
        for (int it = 0; it < 2; it++) {
            int item = lane + it * 32;
            if (item < 49) {
                int r = item / 7, c = item % 7;
                if (!(r >= 2 && r <= 4 && c >= 2 && c <= 4)) {
                    int rr = ry + 23 + r; if (rr >= 25) rr -= 25; if (rr >= 25) rr -= 25;
                    int cc = rx + 23 + c; if (cc >= 25) cc -= 25; if (cc >= 25) cc -= 25;
                    if (xb[rr * 25 + cc] != 0.0f) pf |= 1ULL << (r * 8 + c);
                }
            }
        }
        u64 f = REDOR64(pf);
        if (lane == 0) s_fixed = f;
    } else if (warp == 1) {
        // 5x5 target window (v in [24,52]).
        const float* __restrict__ tb = target + b * 625;
        u64 pt = 0;
        if (lane < 25) {
            int r = lane / 5, c = lane % 5;
            int rr = ry + 24 + r; if (rr >= 25) rr -= 25; if (rr >= 25) rr -= 25;
            int cc = rx + 24 + c; if (cc >= 25) cc -= 25; if (cc >= 25) cc -= 25;
            if (tb[rr * 25 + cc] != 0.0f) pt |= 1ULL << ((r + 1) * 8 + (c + 1));
        }
        u64 tg = REDOR64(pt);
        if (lane == 0) s_targ = tg;
    }

    // ---- Non-critical loads after the gather issue ----
    const float4 nz = ((const float4*)noise)[b * 128 + tid];

    float x0 = xb[tid];
    float x1 = xb[tid + 128];
    float x2 = xb[tid + 256];
    float x3 = xb[tid + 384];
    float x4 = (tid < 113) ? xb[tid + 512] : 0.0f;

    // Copy x -> out.
    ob[tid]       = x0;
    ob[tid + 128] = x1;
    ob[tid + 256] = x2;
    ob[tid + 384] = x3;
    if (tid < 113) ob[tid + 512] = x4;

    // Base pattern mask: p = 4*tid + j; element k (r=k/3,c=k%3) = (p>>(8-k))&1
    // at board bit (2+r)*8+(2+c).  tid bits 6..0 -> board bits
    // 18,19,20 (row0, reversed triple), 26,27,28 (row1, reversed), 34.
    const u64 base = ((u64)(__brev((tid >> 4) & 7) >> 29) << 18)
                   | ((u64)(__brev((tid >> 1) & 7) >> 29) << 26)
                   | ((u64)(tid & 1) << 34);

    __syncthreads();

    const u64 targ = s_targ;
    const u64 Bc   = s_fixed | base;            // board without bits 35/36
    const u64 M    = 0x007F7F7F7F7F7F7FULL;     // col-shift guard
    const u64 CROP = 0x00003E3E3E3E3E00ULL;     // rows 1..5, cols 1..5
    const u64 B35  = 1ULL << 35, B36 = 1ULL << 36;
    // Constant neighbor masks of center cells (4,3) and (4,4):
    const u64 M35 = 0x00001C141C000000ULL;
    const u64 M36 = 0x0000382838000000ULL;

    // One CSA over the 8 neighbor planes of Bc -> bit-sliced count:
    //   cc0 = count bit0, cc1 = parity of weight-2 sum, hi = sum >= 2.
    // alive: cc1 & ~hi & (cc0 | cell).
    u64 n1 = (Bc << 1) & M, n2 = (Bc >> 1) & M;
    u64 n3 = Bc << 8,  n4 = Bc >> 8;
    u64 n5 = n1 << 8,  n6 = n1 >> 8;
    u64 n7 = n2 << 8,  n8 = n2 >> 8;

    u64 a1 = n1 ^ n2, b1 = n1 & n2;
    u64 a2 = n3 ^ n4, b2 = n3 & n4;
    u64 a3 = n5 ^ n6, b3 = n5 & n6;
    u64 a4 = n7 ^ n8, b4 = n7 & n8;

    u64 s1 = a1 ^ a2, t1 = a1 & a2;
    u64 s2 = a3 ^ a4, t2 = a3 & a4;
    u64 cc0 = s1 ^ s2, u0 = s1 & s2;

    u64 p1 = b1 ^ b2, q1 = b1 & b2;
    u64 p2 = b3 ^ b4, q2 = b3 & b4;
    u64 p3 = t1 ^ t2, q3 = t1 & t2;
    u64 r1 = p1 ^ p2, w1 = p1 & p2;
    u64 r2 = p3 ^ u0, w2 = p3 & u0;
    u64 cc1 = r1 ^ r2, w3 = r1 & r2;
    u64 hi = q1 | q2 | q3 | w1 | w2 | w3;

    u64 bestKey = ~0ULL;

#define FIN(NEXT, P, NZS)                                                    \
    {                                                                        \
        int err = __popcll(((NEXT) & CROP) ^ targ);                          \
        float sd = (float)err + (NZS) * 0.5f;                                \
        u64 key = ((u64)__float_as_uint(sd) << 32) | (unsigned)(P);          \
        if (key < bestKey) bestKey = key;                                    \
    }

    // j=0: no toggles.
    {
        u64 nx = cc1 & ~hi & (cc0 | Bc);
        FIN(nx, 4 * tid + 0, nz.x)
    }
    // j=1: +bit36 -> ripple-add M36.
    {
        u64 k0 = cc0 & M36, a0v = cc0 ^ M36;
        u64 av = cc1 ^ k0,  h   = hi | (cc1 & k0);
        u64 nx = av & ~h & (a0v | Bc | B36);
        FIN(nx, 4 * tid + 1, nz.y)
    }
    // j=2: +bit35 -> ripple-add M35.
    {
        u64 k0 = cc0 & M35, a0v = cc0 ^ M35;
        u64 av = cc1 ^ k0,  h   = hi | (cc1 & k0);
        u64 nx = av & ~h & (a0v | Bc | B35);
        FIN(nx, 4 * tid + 2, nz.z)
    }
    // j=3: +bit35 then +bit36 (sequential ripple adds, exact).
    {
        u64 k0 = cc0 & M35, a0v = cc0 ^ M35;
        u64 av = cc1 ^ k0,  h1  = hi | (cc1 & k0);
        u64 k1 = a0v & M36, g0  = a0v ^ M36;
        u64 gv = av ^ k1,   h2  = h1 | (av & k1);
        u64 nx = gv & ~h2 & (g0 | Bc | B35 | B36);
        FIN(nx, 4 * tid + 3, nz.w)
    }
#undef FIN

    // Warp argmin (packed key => value min, first-index tiebreak).
    #pragma unroll
    for (int s = 16; s; s >>= 1) {
        u64 o = __shfl_xor_sync(0xffffffffu, bestKey, s);
        if (o < bestKey) bestKey = o;
    }
    if (lane == 0) sk[warp] = bestKey;

    __syncthreads();   // publishes sk; orders copy stores before patch

    if (tid < 9) {
        u64 k0 = sk[0];
        if (sk[1] < k0) k0 = sk[1];
        if (sk[2] < k0) k0 = sk[2];
        if (sk[3] < k0) k0 = sk[3];
        int best = (int)(unsigned)k0;
        float vv = ((best >> (8 - tid)) & 1) ? 1.0f : 0.0f;
        ob[(ry + tid / 3) * 25 + (rx + tid % 3)] = vv;
    }
}

extern "C" void kernel_launch(void* const* d_in, const int* in_sizes, int n_in,
                              void* d_out, int out_size)
{
    const float* x      = (const float*)d_in[0];
    const float* target = (const float*)d_in[1];
    const float* noise  = (const float*)d_in[2];
    const int*   ryp    = (const int*)d_in[3];
    const int*   rxp    = (const int*)d_in[4];
    float* out = (float*)d_out;

    int B = in_sizes[0] / 625;
    bcl_kernel<<<B, 128>>>(x, target, noise, ryp, rxp, out);
}